// round 1
// baseline (speedup 1.0000x reference)
#include <cuda_runtime.h>
#include <cuda_bf16.h>
#include <cstdint>

// Problem constants
#define NN 16384
#define DD 256

// GEMM-LSE tiling
#define BM 64
#define BN 128
#define KB 16
#define THREADS 256

// Scratch: normalized + transposed features, [d][n] layout
__device__ float g_flT[DD * NN];  // 16 MB
__device__ float g_fgT[DD * NN];  // 16 MB
__device__ float g_bsum[NN / BM]; // per-block loss sums (256)

__device__ __forceinline__ float ex2f(float x) {
    float y; asm("ex2.approx.ftz.f32 %0, %1;" : "=f"(y) : "f"(x)); return y;
}
__device__ __forceinline__ float lg2f(float x) {
    float y; asm("lg2.approx.ftz.f32 %0, %1;" : "=f"(y) : "f"(x)); return y;
}

// ---------------------------------------------------------------------------
// Kernel A: L2-normalize each row, store transposed into g_flT / g_fgT.
// One warp per row; 8 warps per block.
// ---------------------------------------------------------------------------
__global__ void __launch_bounds__(256) norm_t_kernel(const float* __restrict__ in, int which) {
    float* __restrict__ outT = which ? g_fgT : g_flT;
    const int wid = threadIdx.x >> 5;
    const int lane = threadIdx.x & 31;
    const int row = blockIdx.x * 8 + wid;

    const float4* r4 = (const float4*)(in + (size_t)row * DD);
    float4 v0 = r4[lane];
    float4 v1 = r4[lane + 32];

    float ss = v0.x * v0.x + v0.y * v0.y + v0.z * v0.z + v0.w * v0.w
             + v1.x * v1.x + v1.y * v1.y + v1.z * v1.z + v1.w * v1.w;
    #pragma unroll
    for (int off = 16; off > 0; off >>= 1)
        ss += __shfl_xor_sync(0xffffffffu, ss, off);

    float norm = sqrtf(ss);
    float s = 1.0f / fmaxf(norm, 1e-12f);

    // v0 covers d = lane*4 + c, v1 covers d = 128 + lane*4 + c
    const int d0 = lane * 4;
    outT[(size_t)(d0 + 0) * NN + row] = v0.x * s;
    outT[(size_t)(d0 + 1) * NN + row] = v0.y * s;
    outT[(size_t)(d0 + 2) * NN + row] = v0.z * s;
    outT[(size_t)(d0 + 3) * NN + row] = v0.w * s;
    outT[(size_t)(128 + d0 + 0) * NN + row] = v1.x * s;
    outT[(size_t)(128 + d0 + 1) * NN + row] = v1.y * s;
    outT[(size_t)(128 + d0 + 2) * NN + row] = v1.z * s;
    outT[(size_t)(128 + d0 + 3) * NN + row] = v1.w * s;
}

// ---------------------------------------------------------------------------
// Kernel B: fused GEMM + sum-of-exp + diagonal capture.
// Each CTA owns BM=64 rows; loops over all 128 column tiles of BN=128.
// A block (64 rows x 256 k) lives in shared for the whole CTA.
// B streamed in KB=16 k-slices with register prefetch.
// ---------------------------------------------------------------------------
__global__ void __launch_bounds__(THREADS, 2) gemm_lse_kernel() {
    extern __shared__ float smem[];
    float* As   = smem;                    // [k][r]: k*64 + r   (256*64 = 16384 f)
    float* Bs   = As + DD * BM;            // [kk][c]: kk*128 + c (16*128 = 2048 f)
    float* ssum = Bs + KB * BN;            // [64][17]           (1088 f)
    float* sdiag = ssum + BM * 17;         // [64]
    float* sloss = sdiag + BM;             // [64]

    const int tid = threadIdx.x;
    const int tx = tid & 15;        // 16 col-threads -> 8 cols each
    const int ty = tid >> 4;        // 16 row-threads -> 4 rows each
    const int bx = blockIdx.x;
    const int rowBase = bx * BM;

    // ---- Load the full A block into shared ([k][r], straight copy of g_flT slice)
    #pragma unroll
    for (int i = 0; i < 16; i++) {
        int idx = tid + THREADS * i;       // 4096 float4s total
        int k = idx >> 4;
        int f = idx & 15;
        float4 v = *(const float4*)(g_flT + (size_t)k * NN + rowBase + f * 4);
        *(float4*)(As + k * BM + f * 4) = v;
    }
    __syncthreads();

    const float K2 = (float)(1.0 / (0.07 * 0.6931471805599453)); // 1/(T*ln2)

    float rowsum[4] = {0.f, 0.f, 0.f, 0.f};

    // B prefetch thread addressing: 512 float4s per k-slice, 2 per thread
    const int bk0 = tid >> 5;          // k row within slice (0..7)
    const int bf  = tid & 31;          // float4 within row (0..31)

    for (int ct = 0; ct < NN / BN; ct++) {
        const int colBase = ct * BN;
        float acc[4][8];
        #pragma unroll
        for (int i = 0; i < 4; i++)
            #pragma unroll
            for (int j = 0; j < 8; j++) acc[i][j] = 0.f;

        // prefetch k-slice 0
        float4 p0 = *(const float4*)(g_fgT + (size_t)(bk0)     * NN + colBase + bf * 4);
        float4 p1 = *(const float4*)(g_fgT + (size_t)(bk0 + 8) * NN + colBase + bf * 4);

        for (int kt = 0; kt < DD / KB; kt++) {
            __syncthreads();   // previous slice's compute done
            *(float4*)(Bs + (bk0)     * BN + bf * 4) = p0;
            *(float4*)(Bs + (bk0 + 8) * BN + bf * 4) = p1;
            __syncthreads();

            if (kt < DD / KB - 1) {
                int kbase = (kt + 1) * KB;
                p0 = *(const float4*)(g_fgT + (size_t)(kbase + bk0)     * NN + colBase + bf * 4);
                p1 = *(const float4*)(g_fgT + (size_t)(kbase + bk0 + 8) * NN + colBase + bf * 4);
            }

            #pragma unroll
            for (int kk = 0; kk < KB; kk++) {
                const float4 a  = *(const float4*)(As + (kt * KB + kk) * BM + ty * 4);
                const float4 b0 = *(const float4*)(Bs + kk * BN + tx * 8);
                const float4 b1 = *(const float4*)(Bs + kk * BN + tx * 8 + 4);
                float av[4] = {a.x, a.y, a.z, a.w};
                float bv[8] = {b0.x, b0.y, b0.z, b0.w, b1.x, b1.y, b1.z, b1.w};
                #pragma unroll
                for (int i = 0; i < 4; i++)
                    #pragma unroll
                    for (int j = 0; j < 8; j++)
                        acc[i][j] = fmaf(av[i], bv[j], acc[i][j]);
            }
        }

        // diagonal capture: global row == global col happens only when ct == bx/2
        if (ct == (bx >> 1)) {
            const int off = (bx & 1) << 6;      // 0 or 64: local col of diagonal
            #pragma unroll
            for (int i = 0; i < 4; i++) {
                int dcol = off + ty * 4 + i;    // local col of this row's diagonal
                if ((dcol >> 3) == tx)
                    sdiag[ty * 4 + i] = acc[i][dcol & 7];
            }
        }

        // accumulate sum of exp (base-2, pre-scaled logits)
        #pragma unroll
        for (int i = 0; i < 4; i++) {
            float s = 0.f;
            #pragma unroll
            for (int j = 0; j < 8; j++)
                s += ex2f(acc[i][j] * K2);
            rowsum[i] += s;
        }
    }

    __syncthreads();   // sdiag fully written, Bs no longer needed
    #pragma unroll
    for (int i = 0; i < 4; i++)
        ssum[(ty * 4 + i) * 17 + tx] = rowsum[i];
    __syncthreads();

    if (tid < BM) {
        const int r = tid;
        float s2 = 0.f;
        #pragma unroll
        for (int t = 0; t < 16; t++) s2 += ssum[r * 17 + t];
        float lse = 0.6931471805599453f * lg2f(s2);      // natural log
        float dot = sdiag[r];
        sloss[r] = lse - dot * 14.285714285714286f;       // -dot/T + lse
    }
    __syncthreads();

    if (tid == 0) {
        float t = 0.f;
        for (int r = 0; r < BM; r++) t += sloss[r];       // fixed order: deterministic
        g_bsum[bx] = t;
    }
}

// ---------------------------------------------------------------------------
// Kernel C: deterministic final reduce -> mean
// ---------------------------------------------------------------------------
__global__ void finalize_kernel(float* __restrict__ out) {
    if (threadIdx.x == 0) {
        float t = 0.f;
        for (int i = 0; i < NN / BM; i++) t += g_bsum[i];
        out[0] = t / (float)NN;
    }
}

// ---------------------------------------------------------------------------
extern "C" void kernel_launch(void* const* d_in, const int* in_sizes, int n_in,
                              void* d_out, int out_size) {
    const float* feat_local  = (const float*)d_in[0];
    const float* feat_global = (const float*)d_in[1];
    float* out = (float*)d_out;

    static bool attr_set = false;
    const int smem_bytes = (DD * BM + KB * BN + BM * 17 + BM + BM) * sizeof(float);
    if (!attr_set) {
        cudaFuncSetAttribute(gemm_lse_kernel,
                             cudaFuncAttributeMaxDynamicSharedMemorySize, smem_bytes);
        attr_set = true;
    }

    norm_t_kernel<<<NN / 8, 256>>>(feat_local, 0);
    norm_t_kernel<<<NN / 8, 256>>>(feat_global, 1);
    gemm_lse_kernel<<<NN / BM, THREADS, smem_bytes>>>();
    finalize_kernel<<<1, 32>>>(out);
}

// round 3
// speedup vs baseline: 18.1103x; 18.1103x over previous
#include <cuda_runtime.h>
#include <cuda_bf16.h>
#include <cstdint>

#define NN 16384
#define DD 256
#define BM 128
#define BN 128
#define NTILES (NN / BN)              // 128
#define TILE_BYTES (BM * DD * 2)      // 65536
#define THREADS 128                   // 4 compute warps

// Packed, normalized bf16 operands: per 128-row tile, row-major 512B rows with
// 16B-chunk XOR swizzle (chunk ^ (row&7)) for conflict-free ldmatrix.
__device__ __align__(128) __nv_bfloat16 g_flB[NN * DD];  // 8 MB, pre-scaled by 1/(T*ln2)
__device__ __align__(128) __nv_bfloat16 g_fgB[NN * DD];  // 8 MB
__device__ float g_bsum[NN / BM];

// ---------------------------------------------------------------------------
__device__ __forceinline__ uint32_t elect_one_pred() {
    uint32_t p;
    asm volatile("{\n\t.reg .pred p;\n\telect.sync _|p, 0xFFFFFFFF;\n\t"
                 "selp.b32 %0, 1, 0, p;\n\t}" : "=r"(p));
    return p;
}
__device__ __forceinline__ uint32_t smem_u32(const void* p) {
    uint32_t a;
    asm("{ .reg .u64 t; cvta.to.shared.u64 t, %1; cvt.u32.u64 %0, t; }" : "=r"(a) : "l"(p));
    return a;
}
__device__ __forceinline__ float ex2f(float x) {
    float y; asm("ex2.approx.ftz.f32 %0, %1;" : "=f"(y) : "f"(x)); return y;
}
__device__ __forceinline__ float lg2f(float x) {
    float y; asm("lg2.approx.ftz.f32 %0, %1;" : "=f"(y) : "f"(x)); return y;
}

#define MBARRIER_INIT(mbar, count) \
    asm volatile("mbarrier.init.shared.b64 [%0], %1;" :: "r"((uint32_t)(mbar)), "r"((uint32_t)(count)) : "memory")
#define MBARRIER_EXPECT_TX(mbar, bytes) \
    asm volatile("mbarrier.arrive.expect_tx.shared.b64 _, [%0], %1;" :: "r"((uint32_t)(mbar)), "r"((uint32_t)(bytes)) : "memory")
#define MBARRIER_WAIT_PARITY(mbar, parity) do { \
    uint32_t _m = (uint32_t)(mbar); uint32_t _p = (uint32_t)(parity); uint32_t _d; \
    asm volatile("{\n\t.reg .pred p;\n\t" \
        "mbarrier.try_wait.parity.acquire.cta.shared::cta.b64 p, [%1], %2;\n\t" \
        "selp.b32 %0, 1, 0, p;\n\t}" : "=r"(_d) : "r"(_m), "r"(_p) : "memory"); \
    if (!_d) { \
        asm volatile("{\n\t.reg .pred P1;\n\t" \
            "WL_%=:\n\t" \
            "mbarrier.try_wait.parity.acquire.cta.shared::cta.b64 P1, [%0], %1, 0x989680;\n\t" \
            "@P1 bra.uni WD_%=;\n\t" \
            "bra.uni WL_%=;\n\t" \
            "WD_%=:\n\t}" :: "r"(_m), "r"(_p) : "memory"); \
    } \
} while (0)

__device__ __forceinline__ void bulk_copy(uint32_t dst_smem, const void* src, uint32_t bytes,
                                          uint32_t mbar) {
    asm volatile("cp.async.bulk.shared::cta.global.mbarrier::complete_tx::bytes [%0], [%1], %2, [%3];"
                 :: "r"(dst_smem), "l"(src), "r"(bytes), "r"(mbar) : "memory");
}
__device__ __forceinline__ void ldsm4(uint32_t* r, uint32_t addr) {
    asm volatile("ldmatrix.sync.aligned.m8n8.x4.shared.b16 {%0,%1,%2,%3}, [%4];"
                 : "=r"(r[0]), "=r"(r[1]), "=r"(r[2]), "=r"(r[3]) : "r"(addr));
}
__device__ __forceinline__ void mma16816(float* d, const uint32_t* a, const uint32_t* b) {
    asm volatile("mma.sync.aligned.m16n8k16.row.col.f32.bf16.bf16.f32 "
                 "{%0,%1,%2,%3}, {%4,%5,%6,%7}, {%8,%9}, {%0,%1,%2,%3};"
                 : "+f"(d[0]), "+f"(d[1]), "+f"(d[2]), "+f"(d[3])
                 : "r"(a[0]), "r"(a[1]), "r"(a[2]), "r"(a[3]), "r"(b[0]), "r"(b[1]));
}

// ---------------------------------------------------------------------------
// Kernel A: L2-normalize, scale (A side by 1/(T*ln2)), bf16-pack into swizzled
// tile layout. One warp per row; lane owns one 16B chunk (k = lane*8..+7).
// ---------------------------------------------------------------------------
__global__ void __launch_bounds__(256) norm_pack_kernel(const float* __restrict__ in, int which) {
    char* outB = (char*)(which ? g_fgB : g_flB);
    const float extra = which ? 1.0f : (float)(1.0 / (0.07 * 0.6931471805599453));
    const int wid = threadIdx.x >> 5;
    const int lane = threadIdx.x & 31;
    const int row = blockIdx.x * 8 + wid;

    const float4* r4 = (const float4*)(in + (size_t)row * DD);
    float4 a = r4[2 * lane];
    float4 b = r4[2 * lane + 1];

    float ss = a.x * a.x + a.y * a.y + a.z * a.z + a.w * a.w
             + b.x * b.x + b.y * b.y + b.z * b.z + b.w * b.w;
    #pragma unroll
    for (int off = 16; off > 0; off >>= 1)
        ss += __shfl_xor_sync(0xffffffffu, ss, off);
    float s = extra / fmaxf(sqrtf(ss), 1e-12f);

    __nv_bfloat162 h0 = __floats2bfloat162_rn(a.x * s, a.y * s);
    __nv_bfloat162 h1 = __floats2bfloat162_rn(a.z * s, a.w * s);
    __nv_bfloat162 h2 = __floats2bfloat162_rn(b.x * s, b.y * s);
    __nv_bfloat162 h3 = __floats2bfloat162_rn(b.z * s, b.w * s);
    uint4 packed;
    packed.x = *(uint32_t*)&h0; packed.y = *(uint32_t*)&h1;
    packed.z = *(uint32_t*)&h2; packed.w = *(uint32_t*)&h3;

    const int t = row >> 7;            // tile
    const int r = row & 127;           // local row
    const uint32_t off = (uint32_t)r * 512u + (uint32_t)((lane ^ (r & 7)) << 4);
    *(uint4*)(outB + (size_t)t * TILE_BYTES + off) = packed;
}

// ---------------------------------------------------------------------------
// Kernel B: HMMA GEMM (128x128 CTA tile, 4 warps of 64x64) + fused sum-of-exp
// + diagonal capture. A persistent in smem; B double-buffered via cp.async.bulk.
// ---------------------------------------------------------------------------
__global__ void __launch_bounds__(THREADS, 1) gemm_lse_kernel() {
    extern __shared__ __align__(128) char smem_raw[];
    const uint32_t sbase0 = smem_u32(smem_raw);
    const uint32_t cb = (sbase0 + 1023) & ~1023u;
    char* cptr = smem_raw + (cb - sbase0);

    const uint32_t MB_A = cb + 0;
    const uint32_t MB_B = cb + 8;            // two: +0, +8
    float* diag_s  = (float*)(cptr + 64);    // [128]
    float* red_s   = (float*)(cptr + 576);   // [128][2]
    float* sloss_s = (float*)(cptr + 1664);  // [128]
    const uint32_t A_S = cb + 4096;
    const uint32_t B_S = A_S + TILE_BYTES;   // 2 buffers of 64KB

    const int tid = threadIdx.x;
    const int lane = tid & 31;
    const int w = tid >> 5;
    const int wm = w >> 1;                   // 0/1: M half
    const int wn = w & 1;                    // 0/1: N half
    const int bx = blockIdx.x;

    if (tid == 0) {
        MBARRIER_INIT(MB_A, 1);
        MBARRIER_INIT(MB_B + 0, 1);
        MBARRIER_INIT(MB_B + 8, 1);
    }
    __syncthreads();

    const uint32_t el = (w == 0) ? elect_one_pred() : 0;
    if (el) {
        MBARRIER_EXPECT_TX(MB_A, TILE_BYTES);
        bulk_copy(A_S, (const char*)g_flB + (size_t)bx * TILE_BYTES, TILE_BYTES, MB_A);
        MBARRIER_EXPECT_TX(MB_B + 0, TILE_BYTES);
        bulk_copy(B_S, (const char*)g_fgB, TILE_BYTES, MB_B + 0);
    }

    // ldmatrix addressing
    const uint32_t xl = (uint32_t)(lane & 7);
    const int kbA = (lane >> 4) & 1;   // A: bit4 -> k-half chunk
    const int rbA = (lane >> 3) & 1;   // A: bit3 -> +8 row
    const int kbB = (lane >> 3) & 1;   // B: bit3 -> k-half chunk
    const int rbB = (lane >> 4) & 1;   // B: bit4 -> +8 row
    uint32_t aBase[4], bRow[4];
    #pragma unroll
    for (int mf = 0; mf < 4; mf++)
        aBase[mf] = A_S + (uint32_t)(wm * 64 + mf * 16 + (lane & 7) + rbA * 8) * 512u;
    #pragma unroll
    for (int nf2 = 0; nf2 < 4; nf2++)
        bRow[nf2] = (uint32_t)(wn * 64 + nf2 * 16 + (lane & 7) + rbB * 8) * 512u;

    float rs[8];
    #pragma unroll
    for (int j = 0; j < 8; j++) rs[j] = 0.0f;

    MBARRIER_WAIT_PARITY(MB_A, 0);

    for (int i = 0; i < NTILES; i++) {
        const int s = i & 1;
        if (el && i + 1 < NTILES) {
            const int s2 = (i + 1) & 1;
            MBARRIER_EXPECT_TX(MB_B + s2 * 8, TILE_BYTES);
            bulk_copy(B_S + (uint32_t)s2 * TILE_BYTES,
                      (const char*)g_fgB + (size_t)(i + 1) * TILE_BYTES, TILE_BYTES,
                      MB_B + s2 * 8);
        }
        MBARRIER_WAIT_PARITY(MB_B + s * 8, (i >> 1) & 1);

        const uint32_t bBase = B_S + (uint32_t)s * TILE_BYTES;

        float acc[4][8][4];
        #pragma unroll
        for (int mf = 0; mf < 4; mf++)
            #pragma unroll
            for (int nf = 0; nf < 8; nf++)
                #pragma unroll
                for (int c = 0; c < 4; c++) acc[mf][nf][c] = 0.0f;

        #pragma unroll
        for (int ks = 0; ks < 16; ks++) {
            uint32_t afrag[4][4], bfrag[4][4];
            const uint32_t cA = (uint32_t)((2 * ks + kbA) ^ (int)xl) << 4;
            const uint32_t cB = (uint32_t)((2 * ks + kbB) ^ (int)xl) << 4;
            #pragma unroll
            for (int mf = 0; mf < 4; mf++) ldsm4(afrag[mf], aBase[mf] + cA);
            #pragma unroll
            for (int nf2 = 0; nf2 < 4; nf2++) ldsm4(bfrag[nf2], bBase + bRow[nf2] + cB);
            #pragma unroll
            for (int mf = 0; mf < 4; mf++)
                #pragma unroll
                for (int nf2 = 0; nf2 < 4; nf2++) {
                    mma16816(acc[mf][nf2 * 2],     afrag[mf], &bfrag[nf2][0]);
                    mma16816(acc[mf][nf2 * 2 + 1], afrag[mf], &bfrag[nf2][2]);
                }
        }

        __syncthreads();   // all smem reads of this tile done -> buffers reusable

        if (i == bx && wm == wn) {   // diagonal lives where wm==wn
            const int g = lane >> 2, q = lane & 3;
            #pragma unroll
            for (int mf = 0; mf < 4; mf++)
                #pragma unroll
                for (int nf = 0; nf < 8; nf++)
                    #pragma unroll
                    for (int h = 0; h < 2; h++)
                        #pragma unroll
                        for (int cc = 0; cc < 2; cc++) {
                            int R = wm * 64 + mf * 16 + g + h * 8;
                            int C = wn * 64 + nf * 8 + q * 2 + cc;
                            if (R == C) diag_s[R] = acc[mf][nf][h * 2 + cc];
                        }
        }

        #pragma unroll
        for (int mf = 0; mf < 4; mf++)
            #pragma unroll
            for (int nf = 0; nf < 8; nf++) {
                rs[mf * 2 + 0] += ex2f(acc[mf][nf][0]) + ex2f(acc[mf][nf][1]);
                rs[mf * 2 + 1] += ex2f(acc[mf][nf][2]) + ex2f(acc[mf][nf][3]);
            }
    }

    // reduce row sums: lanes l, l^1, l^2 share the same row
    #pragma unroll
    for (int j = 0; j < 8; j++) {
        rs[j] += __shfl_xor_sync(0xffffffffu, rs[j], 1);
        rs[j] += __shfl_xor_sync(0xffffffffu, rs[j], 2);
    }
    if ((lane & 3) == 0) {
        const int g = lane >> 2;
        #pragma unroll
        for (int mf = 0; mf < 4; mf++)
            #pragma unroll
            for (int h = 0; h < 2; h++) {
                int R = wm * 64 + mf * 16 + g + h * 8;
                red_s[R * 2 + wn] = rs[mf * 2 + h];
            }
    }
    __syncthreads();

    if (tid < 128) {
        const float tot = red_s[tid * 2] + red_s[tid * 2 + 1];
        sloss_s[tid] = 0.6931471805599453f * (lg2f(tot) - diag_s[tid]);
    }
    __syncthreads();
    if (tid == 0) {
        float t = 0.0f;
        #pragma unroll 8
        for (int r = 0; r < BM; r++) t += sloss_s[r];
        g_bsum[bx] = t;
    }
}

// ---------------------------------------------------------------------------
__global__ void finalize_kernel(float* __restrict__ out) {
    __shared__ float sh[128];
    const int t = threadIdx.x;
    sh[t] = g_bsum[t];
    __syncthreads();
    #pragma unroll
    for (int off = 64; off > 0; off >>= 1) {
        if (t < off) sh[t] += sh[t + off];
        __syncthreads();
    }
    if (t == 0) out[0] = sh[0] / (float)NN;
}

// ---------------------------------------------------------------------------
extern "C" void kernel_launch(void* const* d_in, const int* in_sizes, int n_in,
                              void* d_out, int out_size) {
    const float* feat_local  = (const float*)d_in[0];
    const float* feat_global = (const float*)d_in[1];
    float* out = (float*)d_out;

    const int smem_bytes = 1024 + 4096 + 3 * TILE_BYTES;  // 201728
    static bool attr_set = false;
    if (!attr_set) {
        cudaFuncSetAttribute(gemm_lse_kernel,
                             cudaFuncAttributeMaxDynamicSharedMemorySize, smem_bytes);
        attr_set = true;
    }

    norm_pack_kernel<<<NN / 8, 256>>>(feat_local, 0);
    norm_pack_kernel<<<NN / 8, 256>>>(feat_global, 1);
    gemm_lse_kernel<<<NN / BM, THREADS, smem_bytes>>>();
    finalize_kernel<<<1, 128>>>(out);
}

// round 5
// speedup vs baseline: 19.5234x; 1.0780x over previous
#include <cuda_runtime.h>
#include <cuda_bf16.h>
#include <cstdint>

#define NN 16384
#define DD 256
#define BM 128
#define BN 128
#define NTILES (NN / BN)              // 128
#define TILE_BYTES (BM * DD * 2)      // 65536
#define THREADS 256                   // 8 warps: 2 tile-groups of 4

// Packed, normalized bf16 operands: per 128-row tile, row-major 512B rows with
// 16B-chunk XOR swizzle (chunk ^ (row&7)) for conflict-free ldmatrix.
__device__ __align__(128) __nv_bfloat16 g_flB[NN * DD];  // 8 MB, pre-scaled by 1/(T*ln2)
__device__ __align__(128) __nv_bfloat16 g_fgB[NN * DD];  // 8 MB
__device__ float g_bsum[NN / BM];

// ---------------------------------------------------------------------------
__device__ __forceinline__ uint32_t smem_u32(const void* p) {
    uint32_t a;
    asm("{ .reg .u64 t; cvta.to.shared.u64 t, %1; cvt.u32.u64 %0, t; }" : "=r"(a) : "l"(p));
    return a;
}
__device__ __forceinline__ float ex2f(float x) {
    float y; asm("ex2.approx.ftz.f32 %0, %1;" : "=f"(y) : "f"(x)); return y;
}
__device__ __forceinline__ float lg2f(float x) {
    float y; asm("lg2.approx.ftz.f32 %0, %1;" : "=f"(y) : "f"(x)); return y;
}

#define MBARRIER_INIT(mbar, count) \
    asm volatile("mbarrier.init.shared.b64 [%0], %1;" :: "r"((uint32_t)(mbar)), "r"((uint32_t)(count)) : "memory")
#define MBARRIER_EXPECT_TX(mbar, bytes) \
    asm volatile("mbarrier.arrive.expect_tx.shared.b64 _, [%0], %1;" :: "r"((uint32_t)(mbar)), "r"((uint32_t)(bytes)) : "memory")
#define MBARRIER_WAIT_PARITY(mbar, parity) do { \
    uint32_t _m = (uint32_t)(mbar); uint32_t _p = (uint32_t)(parity); uint32_t _d; \
    asm volatile("{\n\t.reg .pred p;\n\t" \
        "mbarrier.try_wait.parity.acquire.cta.shared::cta.b64 p, [%1], %2;\n\t" \
        "selp.b32 %0, 1, 0, p;\n\t}" : "=r"(_d) : "r"(_m), "r"(_p) : "memory"); \
    if (!_d) { \
        asm volatile("{\n\t.reg .pred P1;\n\t" \
            "WL_%=:\n\t" \
            "mbarrier.try_wait.parity.acquire.cta.shared::cta.b64 P1, [%0], %1, 0x989680;\n\t" \
            "@P1 bra.uni WD_%=;\n\t" \
            "bra.uni WL_%=;\n\t" \
            "WD_%=:\n\t}" :: "r"(_m), "r"(_p) : "memory"); \
    } \
} while (0)
#define BAR_SYNC(id, cnt) \
    asm volatile("bar.sync %0, %1;" :: "r"(id), "r"(cnt) : "memory")

__device__ __forceinline__ void bulk_copy(uint32_t dst_smem, const void* src, uint32_t bytes,
                                          uint32_t mbar) {
    asm volatile("cp.async.bulk.shared::cta.global.mbarrier::complete_tx::bytes [%0], [%1], %2, [%3];"
                 :: "r"(dst_smem), "l"(src), "r"(bytes), "r"(mbar) : "memory");
}
__device__ __forceinline__ void ldsm4(uint32_t* r, uint32_t addr) {
    asm volatile("ldmatrix.sync.aligned.m8n8.x4.shared.b16 {%0,%1,%2,%3}, [%4];"
                 : "=r"(r[0]), "=r"(r[1]), "=r"(r[2]), "=r"(r[3]) : "r"(addr));
}
__device__ __forceinline__ void mma16816(float* d, const uint32_t* a, const uint32_t* b) {
    asm volatile("mma.sync.aligned.m16n8k16.row.col.f32.bf16.bf16.f32 "
                 "{%0,%1,%2,%3}, {%4,%5,%6,%7}, {%8,%9}, {%0,%1,%2,%3};"
                 : "+f"(d[0]), "+f"(d[1]), "+f"(d[2]), "+f"(d[3])
                 : "r"(a[0]), "r"(a[1]), "r"(a[2]), "r"(a[3]), "r"(b[0]), "r"(b[1]));
}

// ---------------------------------------------------------------------------
// Kernel A: L2-normalize both tensors, scale A side by 1/(T*ln2), bf16-pack
// into swizzled tile layout. One warp per row. Blocks [0,2048) -> local,
// [2048,4096) -> global.
// ---------------------------------------------------------------------------
__global__ void __launch_bounds__(256) norm_pack_kernel(const float* __restrict__ in_l,
                                                        const float* __restrict__ in_g) {
    const int which = (blockIdx.x >= (NN / 8)) ? 1 : 0;
    const int blk = blockIdx.x - which * (NN / 8);
    const float* __restrict__ in = which ? in_g : in_l;
    char* outB = (char*)(which ? g_fgB : g_flB);
    const float extra = which ? 1.0f : (float)(1.0 / (0.07 * 0.6931471805599453));
    const int wid = threadIdx.x >> 5;
    const int lane = threadIdx.x & 31;
    const int row = blk * 8 + wid;

    const float4* r4 = (const float4*)(in + (size_t)row * DD);
    float4 a = r4[2 * lane];
    float4 b = r4[2 * lane + 1];

    float ss = a.x * a.x + a.y * a.y + a.z * a.z + a.w * a.w
             + b.x * b.x + b.y * b.y + b.z * b.z + b.w * b.w;
    #pragma unroll
    for (int off = 16; off > 0; off >>= 1)
        ss += __shfl_xor_sync(0xffffffffu, ss, off);
    float s = extra / fmaxf(sqrtf(ss), 1e-12f);

    __nv_bfloat162 h0 = __floats2bfloat162_rn(a.x * s, a.y * s);
    __nv_bfloat162 h1 = __floats2bfloat162_rn(a.z * s, a.w * s);
    __nv_bfloat162 h2 = __floats2bfloat162_rn(b.x * s, b.y * s);
    __nv_bfloat162 h3 = __floats2bfloat162_rn(b.z * s, b.w * s);
    uint4 packed;
    packed.x = *(uint32_t*)&h0; packed.y = *(uint32_t*)&h1;
    packed.z = *(uint32_t*)&h2; packed.w = *(uint32_t*)&h3;

    const int t = row >> 7;            // tile
    const int r = row & 127;           // local row
    const uint32_t off = (uint32_t)r * 512u + (uint32_t)((lane ^ (r & 7)) << 4);
    *(uint4*)(outB + (size_t)t * TILE_BYTES + off) = packed;
}

// ---------------------------------------------------------------------------
// Kernel B: HMMA GEMM + fused LSE. Two tile-groups of 4 warps each alternate
// n-tiles so tensor / MUFU / LSU pipes overlap across groups on each SMSP.
// ---------------------------------------------------------------------------
__global__ void __launch_bounds__(THREADS, 1) gemm_lse_kernel() {
    extern __shared__ __align__(128) char smem_raw[];
    const uint32_t sbase0 = smem_u32(smem_raw);
    const uint32_t cb = (sbase0 + 1023) & ~1023u;
    char* cptr = smem_raw + (cb - sbase0);

    const uint32_t MB_A = cb + 0;
    const uint32_t MB_F = cb + 8;            // full barriers: +0 (buf0), +8 (buf1)
    float* diag_s  = (float*)(cptr + 64);    // [128]
    float* red_s   = (float*)(cptr + 576);   // [128][4]
    float* sloss_s = (float*)(cptr + 2624);  // [128]
    const uint32_t A_S = cb + 4096;
    const uint32_t B_S = A_S + TILE_BYTES;   // 2 buffers of 64KB

    const int tid = threadIdx.x;
    const int lane = tid & 31;
    const int w = tid >> 5;
    const int g = w >> 2;                    // tile-group 0/1
    const int wl = w & 3;                    // warp within group
    const int wm = wl >> 1;                  // M half
    const int wn = wl & 1;                   // N half
    const int bx = blockIdx.x;

    if (tid == 0) {
        MBARRIER_INIT(MB_A, 1);
        MBARRIER_INIT(MB_F + 0, 1);
        MBARRIER_INIT(MB_F + 8, 1);
    }
    __syncthreads();

    if (tid == 0) {
        MBARRIER_EXPECT_TX(MB_A, TILE_BYTES);
        bulk_copy(A_S, (const char*)g_flB + (size_t)bx * TILE_BYTES, TILE_BYTES, MB_A);
        MBARRIER_EXPECT_TX(MB_F + 0, TILE_BYTES);
        bulk_copy(B_S, (const char*)g_fgB, TILE_BYTES, MB_F + 0);
        MBARRIER_EXPECT_TX(MB_F + 8, TILE_BYTES);
        bulk_copy(B_S + TILE_BYTES, (const char*)g_fgB + TILE_BYTES, TILE_BYTES, MB_F + 8);
    }

    // ldmatrix addressing
    const uint32_t xl = (uint32_t)(lane & 7);
    const int kbA = (lane >> 4) & 1;
    const int rbA = (lane >> 3) & 1;
    const int kbB = (lane >> 3) & 1;
    const int rbB = (lane >> 4) & 1;
    uint32_t aBase[4], bRow[4];
    #pragma unroll
    for (int mf = 0; mf < 4; mf++)
        aBase[mf] = A_S + (uint32_t)(wm * 64 + mf * 16 + (lane & 7) + rbA * 8) * 512u;
    #pragma unroll
    for (int nf2 = 0; nf2 < 4; nf2++)
        bRow[nf2] = (uint32_t)(wn * 64 + nf2 * 16 + (lane & 7) + rbB * 8) * 512u;

    const uint32_t myF = MB_F + (uint32_t)g * 8;
    const uint32_t bBase = B_S + (uint32_t)g * TILE_BYTES;

    float rs[8];
    #pragma unroll
    for (int j = 0; j < 8; j++) rs[j] = 0.0f;

    MBARRIER_WAIT_PARITY(MB_A, 0);

    for (int j = 0; j < NTILES / 2; j++) {
        const int i = 2 * j + g;
        MBARRIER_WAIT_PARITY(myF, j & 1);

        float acc[4][8][4];
        #pragma unroll
        for (int mf = 0; mf < 4; mf++)
            #pragma unroll
            for (int nf = 0; nf < 8; nf++)
                #pragma unroll
                for (int c = 0; c < 4; c++) acc[mf][nf][c] = 0.0f;

        #pragma unroll
        for (int ks = 0; ks < 16; ks++) {
            uint32_t afrag[4][4], bfrag[4][4];
            const uint32_t cA = (uint32_t)((2 * ks + kbA) ^ (int)xl) << 4;
            const uint32_t cB = (uint32_t)((2 * ks + kbB) ^ (int)xl) << 4;
            #pragma unroll
            for (int mf = 0; mf < 4; mf++) ldsm4(afrag[mf], aBase[mf] + cA);
            #pragma unroll
            for (int nf2 = 0; nf2 < 4; nf2++) ldsm4(bfrag[nf2], bBase + bRow[nf2] + cB);
            #pragma unroll
            for (int mf = 0; mf < 4; mf++)
                #pragma unroll
                for (int nf2 = 0; nf2 < 4; nf2++) {
                    mma16816(acc[mf][nf2 * 2],     afrag[mf], &bfrag[nf2][0]);
                    mma16816(acc[mf][nf2 * 2 + 1], afrag[mf], &bfrag[nf2][2]);
                }
        }

        BAR_SYNC(1 + g, 128);   // this group's smem reads done -> buffer reusable

        if (w == (g << 2) && lane == 0 && j + 1 < NTILES / 2) {
            MBARRIER_EXPECT_TX(myF, TILE_BYTES);
            bulk_copy(bBase, (const char*)g_fgB + (size_t)(i + 2) * TILE_BYTES,
                      TILE_BYTES, myF);
        }

        if (i == bx && wm == wn) {   // diagonal tile for this CTA
            const int gq = lane >> 2, q = lane & 3;
            #pragma unroll
            for (int mf = 0; mf < 4; mf++)
                #pragma unroll
                for (int nf = 0; nf < 8; nf++)
                    #pragma unroll
                    for (int h = 0; h < 2; h++)
                        #pragma unroll
                        for (int cc = 0; cc < 2; cc++) {
                            int R = wm * 64 + mf * 16 + gq + h * 8;
                            int C = wn * 64 + nf * 8 + q * 2 + cc;
                            if (R == C) diag_s[R] = acc[mf][nf][h * 2 + cc];
                        }
        }

        #pragma unroll
        for (int mf = 0; mf < 4; mf++)
            #pragma unroll
            for (int nf = 0; nf < 8; nf++) {
                rs[mf * 2 + 0] += ex2f(acc[mf][nf][0]) + ex2f(acc[mf][nf][1]);
                rs[mf * 2 + 1] += ex2f(acc[mf][nf][2]) + ex2f(acc[mf][nf][3]);
            }
    }

    // reduce row sums within warp: lanes l, l^1, l^2 share the same rows
    #pragma unroll
    for (int j = 0; j < 8; j++) {
        rs[j] += __shfl_xor_sync(0xffffffffu, rs[j], 1);
        rs[j] += __shfl_xor_sync(0xffffffffu, rs[j], 2);
    }
    if ((lane & 3) == 0) {
        const int gq = lane >> 2;
        #pragma unroll
        for (int mf = 0; mf < 4; mf++)
            #pragma unroll
            for (int h = 0; h < 2; h++) {
                int R = wm * 64 + mf * 16 + gq + h * 8;
                red_s[R * 4 + wn * 2 + g] = rs[mf * 2 + h];
            }
    }
    __syncthreads();

    if (tid < 128) {
        const float tot = red_s[tid * 4] + red_s[tid * 4 + 1]
                        + red_s[tid * 4 + 2] + red_s[tid * 4 + 3];
        sloss_s[tid] = 0.6931471805599453f * (lg2f(tot) - diag_s[tid]);
    }
    __syncthreads();
    if (tid == 0) {
        float t = 0.0f;
        #pragma unroll 8
        for (int r = 0; r < BM; r++) t += sloss_s[r];
        g_bsum[bx] = t;
    }
}

// ---------------------------------------------------------------------------
__global__ void finalize_kernel(float* __restrict__ out) {
    __shared__ float sh[128];
    const int t = threadIdx.x;
    sh[t] = g_bsum[t];
    __syncthreads();
    #pragma unroll
    for (int off = 64; off > 0; off >>= 1) {
        if (t < off) sh[t] += sh[t + off];
        __syncthreads();
    }
    if (t == 0) out[0] = sh[0] / (float)NN;
}

// ---------------------------------------------------------------------------
extern "C" void kernel_launch(void* const* d_in, const int* in_sizes, int n_in,
                              void* d_out, int out_size) {
    const float* feat_local  = (const float*)d_in[0];
    const float* feat_global = (const float*)d_in[1];
    float* out = (float*)d_out;

    const int smem_bytes = 1024 + 4096 + 3 * TILE_BYTES;  // 201728
    static bool attr_set = false;
    if (!attr_set) {
        cudaFuncSetAttribute(gemm_lse_kernel,
                             cudaFuncAttributeMaxDynamicSharedMemorySize, smem_bytes);
        attr_set = true;
    }

    norm_pack_kernel<<<2 * (NN / 8), 256>>>(feat_local, feat_global);
    gemm_lse_kernel<<<NN / BM, THREADS, smem_bytes>>>();
    finalize_kernel<<<1, 128>>>(out);
}